// round 11
// baseline (speedup 1.0000x reference)
#include <cuda_runtime.h>
#include <cuda_bf16.h>
#include <mma.h>
#include <cstdint>

using namespace nvcuda;

#define N_NODES 100000
#define N_EDGES_MAX 1600000
#define IN_FEATS 128
#define HMAX 256

// ---- bf16 hi/lo plane scratch (allocation-free rule: __device__ globals) ----
__device__ __nv_bfloat16 g_xh[(size_t)N_NODES * IN_FEATS];
__device__ __nv_bfloat16 g_xl[(size_t)N_NODES * IN_FEATS];
__device__ __nv_bfloat16 g_h1h[(size_t)N_NODES * HMAX];
__device__ __nv_bfloat16 g_h1l[(size_t)N_NODES * HMAX];
__device__ __nv_bfloat16 g_h2h[(size_t)N_NODES * HMAX];
__device__ __nv_bfloat16 g_h2l[(size_t)N_NODES * HMAX];
__device__ __nv_bfloat16 g_nh[(size_t)N_NODES * HMAX];
__device__ __nv_bfloat16 g_nl[(size_t)N_NODES * HMAX];
__device__ float g_z[(size_t)N_NODES * 64];
__device__ __nv_bfloat16 g_w1h[256 * 256], g_w1l[256 * 256];
__device__ __nv_bfloat16 g_w2h[256 * 512], g_w2l[256 * 512];
__device__ __nv_bfloat16 g_w3h[64 * 512],  g_w3l[64 * 512];

__device__ int   g_deg[N_NODES];
__device__ float g_invd[N_NODES];
__device__ int   g_rowptr[N_NODES + 1];
__device__ int   g_pos[N_NODES];
__device__ int   g_csr[N_EDGES_MAX];
__device__ int   g_bsum[128];

// ================= small helpers =================
__device__ __forceinline__ uint32_t smem_u32(const void* p) {
    uint32_t a;
    asm("{ .reg .u64 t; cvta.to.shared.u64 t, %1; cvt.u32.u64 %0, t; }"
        : "=r"(a) : "l"(p));
    return a;
}

__device__ __forceinline__ void cp_async16(uint32_t saddr, const void* gptr, int src_bytes) {
    asm volatile("cp.async.cg.shared.global [%0], [%1], 16, %2;"
                 :: "r"(saddr), "l"(gptr), "r"(src_bytes));
}
#define CP_COMMIT() asm volatile("cp.async.commit_group;" ::: "memory")
#define CP_WAIT0()  asm volatile("cp.async.wait_group 0;" ::: "memory")

__device__ __forceinline__ void bsplit(float v, __nv_bfloat16& h, __nv_bfloat16& l) {
    h = __float2bfloat16_rn(v);
    l = __float2bfloat16_rn(v - __bfloat162float(h));
}

// fp32 -> (hi, lo) planes, 4 elems/thread
__global__ void split4_kernel(const float4* __restrict__ in,
                              __nv_bfloat16* __restrict__ hi,
                              __nv_bfloat16* __restrict__ lo, int n4) {
    int i = blockIdx.x * blockDim.x + threadIdx.x;
    if (i >= n4) return;
    float4 v = in[i];
    __nv_bfloat16 h0, l0, h1, l1, h2, l2, h3, l3;
    bsplit(v.x, h0, l0); bsplit(v.y, h1, l1);
    bsplit(v.z, h2, l2); bsplit(v.w, h3, l3);
    *(__nv_bfloat162*)(hi + i * 4)     = __nv_bfloat162(h0, h1);
    *(__nv_bfloat162*)(hi + i * 4 + 2) = __nv_bfloat162(h2, h3);
    *(__nv_bfloat162*)(lo + i * 4)     = __nv_bfloat162(l0, l1);
    *(__nv_bfloat162*)(lo + i * 4 + 2) = __nv_bfloat162(l2, l3);
}

// ---------------- degree / inverse degree ----------------
__global__ void zero_int_kernel(int* __restrict__ p, int n) {
    int i = blockIdx.x * blockDim.x + threadIdx.x;
    if (i < n) p[i] = 0;
}

__global__ void deg_kernel(const int* __restrict__ dst, int E) {
    int i = blockIdx.x * blockDim.x + threadIdx.x;
    if (i < E) atomicAdd(&g_deg[dst[i]], 1);
}

__global__ void invd_kernel(int n) {
    int i = blockIdx.x * blockDim.x + threadIdx.x;
    if (i < n) g_invd[i] = 1.0f / fmaxf((float)g_deg[i], 1.0f);
}

// ---------------- prefix sum (CSR rowptr) ----------------
#define SCAN_T 1024

__global__ void scan1_kernel(int* __restrict__ excl, int n) {
    __shared__ int s[SCAN_T];
    int i = blockIdx.x * SCAN_T + threadIdx.x;
    int v = (i < n) ? g_deg[i] : 0;
    s[threadIdx.x] = v;
    __syncthreads();
    for (int off = 1; off < SCAN_T; off <<= 1) {
        int t = (threadIdx.x >= off) ? s[threadIdx.x - off] : 0;
        __syncthreads();
        s[threadIdx.x] += t;
        __syncthreads();
    }
    if (i < n) excl[i] = s[threadIdx.x] - v;
    if (threadIdx.x == SCAN_T - 1) g_bsum[blockIdx.x] = s[SCAN_T - 1];
}

__global__ void scan2_kernel(int nb) {
    __shared__ int s[128];
    int v = (threadIdx.x < nb) ? g_bsum[threadIdx.x] : 0;
    s[threadIdx.x] = v;
    __syncthreads();
    for (int off = 1; off < 128; off <<= 1) {
        int t = (threadIdx.x >= off) ? s[threadIdx.x - off] : 0;
        __syncthreads();
        s[threadIdx.x] += t;
        __syncthreads();
    }
    if (threadIdx.x < nb) g_bsum[threadIdx.x] = s[threadIdx.x] - v;  // exclusive
}

__global__ void scan3_kernel(int n, int E) {
    int i = blockIdx.x * blockDim.x + threadIdx.x;
    if (i < n) {
        int r = g_rowptr[i] + g_bsum[i / SCAN_T];
        g_rowptr[i] = r;
        g_pos[i] = r;
    }
    if (i == 0) g_rowptr[n] = E;
}

__global__ void scatter_kernel(const int* __restrict__ src,
                               const int* __restrict__ dst, int E) {
    int i = blockIdx.x * blockDim.x + threadIdx.x;
    if (i < E) {
        int t = dst[i];
        int slot = atomicAdd(&g_pos[t], 1);
        g_csr[slot] = src[i];
    }
}

// ------- pull-style mean aggregation over bf16 hi/lo planes -------
__global__ __launch_bounds__(HMAX)
void agg_split_kernel(const __nv_bfloat16* __restrict__ hHi,
                      const __nv_bfloat16* __restrict__ hLo,
                      __nv_bfloat16* __restrict__ oHi,
                      __nv_bfloat16* __restrict__ oLo, int d) {
    int node = blockIdx.x;
    int tid = threadIdx.x;
    int start = g_rowptr[node];
    int end   = g_rowptr[node + 1];
    __shared__ int sidx[128];
    float acc = 0.f;
    for (int base = start; base < end; base += 128) {
        int n = min(128, end - base);
        if (tid < n) sidx[tid] = g_csr[base + tid];
        __syncthreads();
        int j = 0;
        for (; j + 4 <= n; j += 4) {
            size_t r0 = (size_t)sidx[j + 0] * d + tid;
            size_t r1 = (size_t)sidx[j + 1] * d + tid;
            size_t r2 = (size_t)sidx[j + 2] * d + tid;
            size_t r3 = (size_t)sidx[j + 3] * d + tid;
            acc += __bfloat162float(hHi[r0]) + __bfloat162float(hLo[r0]);
            acc += __bfloat162float(hHi[r1]) + __bfloat162float(hLo[r1]);
            acc += __bfloat162float(hHi[r2]) + __bfloat162float(hLo[r2]);
            acc += __bfloat162float(hHi[r3]) + __bfloat162float(hLo[r3]);
        }
        for (; j < n; j++) {
            size_t r = (size_t)sidx[j] * d + tid;
            acc += __bfloat162float(hHi[r]) + __bfloat162float(hLo[r]);
        }
        __syncthreads();
    }
    float v = acc * g_invd[node];
    __nv_bfloat16 h, l;
    bsplit(v, h, l);
    oHi[(size_t)node * d + tid] = h;
    oLo[(size_t)node * d + tid] = l;
}

// -------- L3 output-side aggregation: out[node] += mean(z[nbrs]), width 64 --------
__global__ __launch_bounds__(64)
void agg_add64_kernel(const float* __restrict__ z, float* __restrict__ out) {
    int node = blockIdx.x;
    int tid = threadIdx.x;
    int start = g_rowptr[node];
    int end   = g_rowptr[node + 1];
    __shared__ int sidx[64];
    float acc = 0.f;
    for (int base = start; base < end; base += 64) {
        int n = min(64, end - base);
        if (tid < n) sidx[tid] = g_csr[base + tid];
        __syncthreads();
        int j = 0;
        for (; j + 4 <= n; j += 4) {
            acc += z[(size_t)sidx[j + 0] * 64 + tid];
            acc += z[(size_t)sidx[j + 1] * 64 + tid];
            acc += z[(size_t)sidx[j + 2] * 64 + tid];
            acc += z[(size_t)sidx[j + 3] * 64 + tid];
        }
        for (; j < n; j++) acc += z[(size_t)sidx[j] * 64 + tid];
        __syncthreads();
    }
    out[(size_t)node * 64 + tid] += acc * g_invd[node];
}

// ================= bf16x3 WMMA GEMM, cp.async double-buffered =================
// out = [A | A_N] @ W^T + bias. All operands pre-split bf16 hi/lo planes.
// D += Ahi*Bhi + Ahi*Blo + Alo*Bhi (fp32 accum).
// CTA 128x128, BK=32, 512 threads = 16 warps (4x4), warp tile 32x32.

#define G_LDT 40
#define G_TILE (128 * G_LDT)           // bf16 elems per plane tile
#define G_BUFB (4 * G_TILE * 2)        // bytes per stage (4 planes)

struct GTiles {
    const __nv_bfloat16 *aHi, *aLo, *bHi, *bLo;
};

__device__ __forceinline__ void gemm_compute_step(
    const __nv_bfloat16* aHi, const __nv_bfloat16* aLo,
    const __nv_bfloat16* bHi, const __nv_bfloat16* bLo,
    int m0, int n0,
    wmma::fragment<wmma::accumulator, 16, 16, 16, float> (&acc)[2][2]) {
    #pragma unroll
    for (int ks = 0; ks < 32; ks += 16) {
        wmma::fragment<wmma::matrix_a, 16, 16, 16, __nv_bfloat16, wmma::row_major> a_hi[2], a_lo[2];
        #pragma unroll
        for (int fm = 0; fm < 2; fm++) {
            wmma::load_matrix_sync(a_hi[fm], aHi + (m0 + fm * 16) * G_LDT + ks, G_LDT);
            wmma::load_matrix_sync(a_lo[fm], aLo + (m0 + fm * 16) * G_LDT + ks, G_LDT);
        }
        #pragma unroll
        for (int fn = 0; fn < 2; fn++) {
            wmma::fragment<wmma::matrix_b, 16, 16, 16, __nv_bfloat16, wmma::col_major> b_hi, b_lo;
            wmma::load_matrix_sync(b_hi, bHi + (n0 + fn * 16) * G_LDT + ks, G_LDT);
            wmma::load_matrix_sync(b_lo, bLo + (n0 + fn * 16) * G_LDT + ks, G_LDT);
            #pragma unroll
            for (int fm = 0; fm < 2; fm++) {
                wmma::mma_sync(acc[fm][fn], a_hi[fm], b_hi, acc[fm][fn]);
                wmma::mma_sync(acc[fm][fn], a_hi[fm], b_lo, acc[fm][fn]);
                wmma::mma_sync(acc[fm][fn], a_lo[fm], b_hi, acc[fm][fn]);
            }
        }
    }
}

// Main GEMM for layers 1-2: Nout=256 (grid.y=2), output split planes + relu.
__global__ __launch_bounds__(512)
void gemm_bf_kernel(const __nv_bfloat16* __restrict__ aHi0, const __nv_bfloat16* __restrict__ aLo0,
                    const __nv_bfloat16* __restrict__ aHi1, const __nv_bfloat16* __restrict__ aLo1,
                    const __nv_bfloat16* __restrict__ wHi,  const __nv_bfloat16* __restrict__ wLo,
                    const float* __restrict__ bias,
                    __nv_bfloat16* __restrict__ outHi, __nv_bfloat16* __restrict__ outLo,
                    int M, int d) {
    constexpr int LDC = 132;
    extern __shared__ char smraw[];
    __nv_bfloat16* tiles = (__nv_bfloat16*)smraw;
    float* Cs = (float*)smraw;
    const uint32_t sb = smem_u32(smraw);

    const int tid = threadIdx.x;
    const int wid = tid >> 5;
    const int m0 = (wid >> 2) * 32;
    const int n0 = (wid & 3) * 32;
    const int bm = blockIdx.x * 128;
    const int bn = blockIdx.y * 128;
    const int K = 2 * d;
    const int nsteps = K / 32;

    const int ar = tid >> 2;            // 0..127
    const int ac = (tid & 3) * 8;       // 0,8,16,24
    const int gm = bm + ar;
    const int asz = (gm < M) ? 16 : 0;
    const uint32_t soff = (uint32_t)(ar * G_LDT + ac) * 2;

    wmma::fragment<wmma::accumulator, 16, 16, 16, float> acc[2][2];
    #pragma unroll
    for (int fm = 0; fm < 2; fm++)
        #pragma unroll
        for (int fn = 0; fn < 2; fn++)
            wmma::fill_fragment(acc[fm][fn], 0.f);

    auto stage = [&](int s) {
        const uint32_t b0 = sb + (uint32_t)(s & 1) * G_BUFB;
        const int k0 = s * 32;
        const __nv_bfloat16 *pah, *pal;
        if (k0 < d) {
            pah = aHi0 + (size_t)gm * d + k0 + ac;
            pal = aLo0 + (size_t)gm * d + k0 + ac;
        } else {
            pah = aHi1 + (size_t)gm * d + (k0 - d) + ac;
            pal = aLo1 + (size_t)gm * d + (k0 - d) + ac;
        }
        cp_async16(b0 + soff,                pah, asz);
        cp_async16(b0 + G_TILE * 2 + soff,   pal, asz);
        const __nv_bfloat16* pbh = wHi + (size_t)(bn + ar) * K + k0 + ac;
        const __nv_bfloat16* pbl = wLo + (size_t)(bn + ar) * K + k0 + ac;
        cp_async16(b0 + 2 * G_TILE * 2 + soff, pbh, 16);
        cp_async16(b0 + 3 * G_TILE * 2 + soff, pbl, 16);
        CP_COMMIT();
    };

    stage(0);
    for (int s = 0; s < nsteps; s++) {
        CP_WAIT0();
        __syncthreads();
        if (s + 1 < nsteps) stage(s + 1);
        const __nv_bfloat16* t = tiles + (size_t)(s & 1) * (4 * G_TILE);
        gemm_compute_step(t, t + G_TILE, t + 2 * G_TILE, t + 3 * G_TILE, m0, n0, acc);
    }

    // ---- epilogue: frags -> Cs -> bias/relu -> split planes ----
    __syncthreads();
    #pragma unroll
    for (int fm = 0; fm < 2; fm++)
        #pragma unroll
        for (int fn = 0; fn < 2; fn++)
            wmma::store_matrix_sync(Cs + (m0 + fm * 16) * LDC + n0 + fn * 16,
                                    acc[fm][fn], LDC, wmma::mem_row_major);
    __syncthreads();

    {
        const int row = tid >> 2;
        const int c0 = (tid & 3) * 32;
        const int gmo = bm + row;
        if (gmo < M) {
            #pragma unroll
            for (int j = 0; j < 8; j++) {
                int c = c0 + j * 4;
                float4 v = *(const float4*)(Cs + row * LDC + c);
                v.x = fmaxf(v.x + bias[bn + c + 0], 0.f);
                v.y = fmaxf(v.y + bias[bn + c + 1], 0.f);
                v.z = fmaxf(v.z + bias[bn + c + 2], 0.f);
                v.w = fmaxf(v.w + bias[bn + c + 3], 0.f);
                __nv_bfloat16 h0, l0, h1, l1, h2, l2, h3, l3;
                bsplit(v.x, h0, l0); bsplit(v.y, h1, l1);
                bsplit(v.z, h2, l2); bsplit(v.w, h3, l3);
                size_t idx = (size_t)gmo * 256 + bn + c;
                *(__nv_bfloat162*)(outHi + idx)     = __nv_bfloat162(h0, h1);
                *(__nv_bfloat162*)(outHi + idx + 2) = __nv_bfloat162(h2, h3);
                *(__nv_bfloat162*)(outLo + idx)     = __nv_bfloat162(l0, l1);
                *(__nv_bfloat162*)(outLo + idx + 2) = __nv_bfloat162(l2, l3);
            }
        }
    }
}

// L3 GEMM: A = h2 planes (K=256), B = stacked [W3self ; W3neigh] (virtual 128 rows).
// cols 0..63 -> out (+bias, fp32), cols 64..127 -> z (fp32).
__global__ __launch_bounds__(512)
void gemm_bf_l3_kernel(const __nv_bfloat16* __restrict__ aHi, const __nv_bfloat16* __restrict__ aLo,
                       const __nv_bfloat16* __restrict__ wHi, const __nv_bfloat16* __restrict__ wLo,
                       const float* __restrict__ bias,
                       float* __restrict__ out, float* __restrict__ z, int M) {
    constexpr int LDC = 132;
    constexpr int Kc = 256;
    extern __shared__ char smraw[];
    __nv_bfloat16* tiles = (__nv_bfloat16*)smraw;
    float* Cs = (float*)smraw;
    const uint32_t sb = smem_u32(smraw);

    const int tid = threadIdx.x;
    const int wid = tid >> 5;
    const int m0 = (wid >> 2) * 32;
    const int n0 = (wid & 3) * 32;
    const int bm = blockIdx.x * 128;
    const int nsteps = Kc / 32;  // 8

    const int ar = tid >> 2;
    const int ac = (tid & 3) * 8;
    const int gm = bm + ar;
    const int asz = (gm < M) ? 16 : 0;
    const uint32_t soff = (uint32_t)(ar * G_LDT + ac) * 2;
    const int wrow = ar & 63;
    const int woff = (ar >> 6) * 256;   // 0 = self, 256 = neighbor half

    wmma::fragment<wmma::accumulator, 16, 16, 16, float> acc[2][2];
    #pragma unroll
    for (int fm = 0; fm < 2; fm++)
        #pragma unroll
        for (int fn = 0; fn < 2; fn++)
            wmma::fill_fragment(acc[fm][fn], 0.f);

    auto stage = [&](int s) {
        const uint32_t b0 = sb + (uint32_t)(s & 1) * G_BUFB;
        const int k0 = s * 32;
        cp_async16(b0 + soff,              aHi + (size_t)gm * Kc + k0 + ac, asz);
        cp_async16(b0 + G_TILE * 2 + soff, aLo + (size_t)gm * Kc + k0 + ac, asz);
        const __nv_bfloat16* pbh = wHi + (size_t)wrow * 512 + woff + k0 + ac;
        const __nv_bfloat16* pbl = wLo + (size_t)wrow * 512 + woff + k0 + ac;
        cp_async16(b0 + 2 * G_TILE * 2 + soff, pbh, 16);
        cp_async16(b0 + 3 * G_TILE * 2 + soff, pbl, 16);
        CP_COMMIT();
    };

    stage(0);
    for (int s = 0; s < nsteps; s++) {
        CP_WAIT0();
        __syncthreads();
        if (s + 1 < nsteps) stage(s + 1);
        const __nv_bfloat16* t = tiles + (size_t)(s & 1) * (4 * G_TILE);
        gemm_compute_step(t, t + G_TILE, t + 2 * G_TILE, t + 3 * G_TILE, m0, n0, acc);
    }

    __syncthreads();
    #pragma unroll
    for (int fm = 0; fm < 2; fm++)
        #pragma unroll
        for (int fn = 0; fn < 2; fn++)
            wmma::store_matrix_sync(Cs + (m0 + fm * 16) * LDC + n0 + fn * 16,
                                    acc[fm][fn], LDC, wmma::mem_row_major);
    __syncthreads();

    {
        const int row = tid >> 2;
        const int c0 = (tid & 3) * 32;   // {0,32}: self -> out; {64,96}: -> z
        const int gmo = bm + row;
        if (gmo < M) {
            if (c0 < 64) {
                #pragma unroll
                for (int j = 0; j < 8; j++) {
                    int c = c0 + j * 4;
                    float4 v = *(const float4*)(Cs + row * LDC + c);
                    v.x += bias[c + 0];
                    v.y += bias[c + 1];
                    v.z += bias[c + 2];
                    v.w += bias[c + 3];
                    *(float4*)(out + (size_t)gmo * 64 + c) = v;
                }
            } else {
                #pragma unroll
                for (int j = 0; j < 8; j++) {
                    int c = c0 + j * 4;
                    float4 v = *(const float4*)(Cs + row * LDC + c);
                    *(float4*)(z + (size_t)gmo * 64 + (c - 64)) = v;
                }
            }
        }
    }
}

extern "C" void kernel_launch(void* const* d_in, const int* in_sizes, int n_in,
                              void* d_out, int out_size) {
    const float* x   = (const float*)d_in[0];
    const int*   src = (const int*)d_in[1];
    const int*   dst = (const int*)d_in[2];
    const float* W1 = (const float*)d_in[3];
    const float* b1 = (const float*)d_in[4];
    const float* W2 = (const float*)d_in[5];
    const float* b2 = (const float*)d_in[6];
    const float* W3 = (const float*)d_in[7];
    const float* b3 = (const float*)d_in[8];
    float* out = (float*)d_out;

    const int E = in_sizes[1];
    const int M = in_sizes[0] / IN_FEATS;   // 100000

    __nv_bfloat16 *xh, *xl, *h1h, *h1l, *h2h, *h2l, *nh, *nl;
    __nv_bfloat16 *w1h, *w1l, *w2h, *w2l, *w3h, *w3l;
    float *z;
    int *deg, *rowptr;
    cudaGetSymbolAddress((void**)&xh,  g_xh);  cudaGetSymbolAddress((void**)&xl,  g_xl);
    cudaGetSymbolAddress((void**)&h1h, g_h1h); cudaGetSymbolAddress((void**)&h1l, g_h1l);
    cudaGetSymbolAddress((void**)&h2h, g_h2h); cudaGetSymbolAddress((void**)&h2l, g_h2l);
    cudaGetSymbolAddress((void**)&nh,  g_nh);  cudaGetSymbolAddress((void**)&nl,  g_nl);
    cudaGetSymbolAddress((void**)&w1h, g_w1h); cudaGetSymbolAddress((void**)&w1l, g_w1l);
    cudaGetSymbolAddress((void**)&w2h, g_w2h); cudaGetSymbolAddress((void**)&w2l, g_w2l);
    cudaGetSymbolAddress((void**)&w3h, g_w3h); cudaGetSymbolAddress((void**)&w3l, g_w3l);
    cudaGetSymbolAddress((void**)&z,   g_z);
    cudaGetSymbolAddress((void**)&deg, g_deg);
    cudaGetSymbolAddress((void**)&rowptr, g_rowptr);

    const int SMEM_G = 2 * G_BUFB;       // 81920 > Cs (67584)
    cudaFuncSetAttribute(gemm_bf_kernel,
                         cudaFuncAttributeMaxDynamicSharedMemorySize, SMEM_G);
    cudaFuncSetAttribute(gemm_bf_l3_kernel,
                         cudaFuncAttributeMaxDynamicSharedMemorySize, SMEM_G);

    const int T = 256;
    const int gx = (M + 127) / 128;

    // ---- one-time splits (x, weights) ----
    {
        int n4 = (M * IN_FEATS) / 4;
        split4_kernel<<<(n4 + T - 1) / T, T>>>((const float4*)x, xh, xl, n4);
        n4 = (256 * 256) / 4;
        split4_kernel<<<(n4 + T - 1) / T, T>>>((const float4*)W1, w1h, w1l, n4);
        n4 = (256 * 512) / 4;
        split4_kernel<<<(n4 + T - 1) / T, T>>>((const float4*)W2, w2h, w2l, n4);
        n4 = (64 * 512) / 4;
        split4_kernel<<<(n4 + T - 1) / T, T>>>((const float4*)W3, w3h, w3l, n4);
    }

    // ---- degrees + CSR build ----
    zero_int_kernel<<<(M + T - 1) / T, T>>>(deg, M);
    deg_kernel<<<(E + T - 1) / T, T>>>(dst, E);
    invd_kernel<<<(M + T - 1) / T, T>>>(M);

    int nb = (M + SCAN_T - 1) / SCAN_T;
    scan1_kernel<<<nb, SCAN_T>>>(rowptr, M);
    scan2_kernel<<<1, 128>>>(nb);
    scan3_kernel<<<(M + T - 1) / T, T>>>(M, E);
    scatter_kernel<<<(E + T - 1) / T, T>>>(src, dst, E);

    // ---- Layer 1: d=128, Nout=256, relu ----
    agg_split_kernel<<<M, IN_FEATS>>>(xh, xl, nh, nl, IN_FEATS);
    gemm_bf_kernel<<<dim3(gx, 2), 512, SMEM_G>>>(xh, xl, nh, nl, w1h, w1l, b1,
                                                 h1h, h1l, M, IN_FEATS);

    // ---- Layer 2: d=256, Nout=256, relu ----
    agg_split_kernel<<<M, 256>>>(h1h, h1l, nh, nl, 256);
    gemm_bf_kernel<<<dim3(gx, 2), 512, SMEM_G>>>(h1h, h1l, nh, nl, w2h, w2l, b2,
                                                 h2h, h2l, M, 256);

    // ---- Layer 3: Nout=64, output-side aggregation ----
    gemm_bf_l3_kernel<<<gx, 512, SMEM_G>>>(h2h, h2l, w3h, w3l, b3, out, z, M);
    agg_add64_kernel<<<M, 64>>>(z, out);
}

// round 12
// speedup vs baseline: 1.3881x; 1.3881x over previous
#include <cuda_runtime.h>
#include <cuda_bf16.h>
#include <mma.h>
#include <cstdint>

using namespace nvcuda;

#define N_NODES 100000
#define N_EDGES_MAX 1600000
#define IN_FEATS 128
#define HMAX 256

// Scratch (allocation-free rule: __device__ globals)
__device__ float g_h1[(size_t)N_NODES * HMAX];
__device__ float g_h2[(size_t)N_NODES * HMAX];
__device__ float g_hN[(size_t)N_NODES * HMAX];
__device__ int   g_deg[N_NODES];
__device__ float g_invd[N_NODES];
__device__ int   g_rowptr[N_NODES + 1];
__device__ int   g_pos[N_NODES];
__device__ int   g_csr[N_EDGES_MAX];
__device__ int   g_bsum[128];

// ---------------- degree / inverse degree ----------------
__global__ void zero_int_kernel(int* __restrict__ p, int n) {
    int i = blockIdx.x * blockDim.x + threadIdx.x;
    if (i < n) p[i] = 0;
}

__global__ void deg_kernel(const int* __restrict__ dst, int E) {
    int i = blockIdx.x * blockDim.x + threadIdx.x;
    if (i < E) atomicAdd(&g_deg[dst[i]], 1);
}

__global__ void invd_kernel(int n) {
    int i = blockIdx.x * blockDim.x + threadIdx.x;
    if (i < n) g_invd[i] = 1.0f / fmaxf((float)g_deg[i], 1.0f);
}

// ---------------- prefix sum (CSR rowptr) ----------------
#define SCAN_T 1024

__global__ void scan1_kernel(int* __restrict__ excl, int n) {
    __shared__ int s[SCAN_T];
    int i = blockIdx.x * SCAN_T + threadIdx.x;
    int v = (i < n) ? g_deg[i] : 0;
    s[threadIdx.x] = v;
    __syncthreads();
    for (int off = 1; off < SCAN_T; off <<= 1) {
        int t = (threadIdx.x >= off) ? s[threadIdx.x - off] : 0;
        __syncthreads();
        s[threadIdx.x] += t;
        __syncthreads();
    }
    if (i < n) excl[i] = s[threadIdx.x] - v;
    if (threadIdx.x == SCAN_T - 1) g_bsum[blockIdx.x] = s[SCAN_T - 1];
}

__global__ void scan2_kernel(int nb) {
    __shared__ int s[128];
    int v = (threadIdx.x < nb) ? g_bsum[threadIdx.x] : 0;
    s[threadIdx.x] = v;
    __syncthreads();
    for (int off = 1; off < 128; off <<= 1) {
        int t = (threadIdx.x >= off) ? s[threadIdx.x - off] : 0;
        __syncthreads();
        s[threadIdx.x] += t;
        __syncthreads();
    }
    if (threadIdx.x < nb) g_bsum[threadIdx.x] = s[threadIdx.x] - v;  // exclusive
}

__global__ void scan3_kernel(int n, int E) {
    int i = blockIdx.x * blockDim.x + threadIdx.x;
    if (i < n) {
        int r = g_rowptr[i] + g_bsum[i / SCAN_T];
        g_rowptr[i] = r;
        g_pos[i] = r;
    }
    if (i == 0) g_rowptr[n] = E;
}

__global__ void scatter_kernel(const int* __restrict__ src,
                               const int* __restrict__ dst, int E) {
    int i = blockIdx.x * blockDim.x + threadIdx.x;
    if (i < E) {
        int t = dst[i];
        int slot = atomicAdd(&g_pos[t], 1);
        g_csr[slot] = src[i];
    }
}

// ============ sync-free group-per-node mean aggregation (LDG.128) ============
// GROUP_LANES threads own one node; thread g covers float4 chunk g of the row.
// CSR index loads are group-uniform (broadcast). No smem, no barriers.
template <int GROUP_LANES, int D>
__global__ __launch_bounds__(256)
void agg_group_kernel(const float* __restrict__ h, float* __restrict__ hN) {
    const int gt = blockIdx.x * blockDim.x + threadIdx.x;
    const int node = gt / GROUP_LANES;
    const int gl = gt % GROUP_LANES;
    if (node >= N_NODES) return;
    const int start = g_rowptr[node];
    const int end   = g_rowptr[node + 1];
    float4 a0 = make_float4(0.f, 0.f, 0.f, 0.f);
    float4 a1 = make_float4(0.f, 0.f, 0.f, 0.f);
    int j = start;
    for (; j + 2 <= end; j += 2) {
        int s0 = g_csr[j];
        int s1 = g_csr[j + 1];
        float4 v0 = *(const float4*)(h + (size_t)s0 * D + gl * 4);
        float4 v1 = *(const float4*)(h + (size_t)s1 * D + gl * 4);
        a0.x += v0.x; a0.y += v0.y; a0.z += v0.z; a0.w += v0.w;
        a1.x += v1.x; a1.y += v1.y; a1.z += v1.z; a1.w += v1.w;
    }
    if (j < end) {
        int s0 = g_csr[j];
        float4 v0 = *(const float4*)(h + (size_t)s0 * D + gl * 4);
        a0.x += v0.x; a0.y += v0.y; a0.z += v0.z; a0.w += v0.w;
    }
    const float inv = g_invd[node];
    float4 r;
    r.x = (a0.x + a1.x) * inv;
    r.y = (a0.y + a1.y) * inv;
    r.z = (a0.z + a1.z) * inv;
    r.w = (a0.w + a1.w) * inv;
    *(float4*)(hN + (size_t)node * D + gl * 4) = r;
}

// L3 output-side: out[node] += mean(z[nbrs]), width 64, 16-lane groups.
__global__ __launch_bounds__(256)
void agg_add64_kernel(const float* __restrict__ z, float* __restrict__ out) {
    const int gt = blockIdx.x * blockDim.x + threadIdx.x;
    const int node = gt >> 4;
    const int gl = gt & 15;
    if (node >= N_NODES) return;
    const int start = g_rowptr[node];
    const int end   = g_rowptr[node + 1];
    float4 a0 = make_float4(0.f, 0.f, 0.f, 0.f);
    float4 a1 = make_float4(0.f, 0.f, 0.f, 0.f);
    int j = start;
    for (; j + 2 <= end; j += 2) {
        int s0 = g_csr[j];
        int s1 = g_csr[j + 1];
        float4 v0 = *(const float4*)(z + (size_t)s0 * 64 + gl * 4);
        float4 v1 = *(const float4*)(z + (size_t)s1 * 64 + gl * 4);
        a0.x += v0.x; a0.y += v0.y; a0.z += v0.z; a0.w += v0.w;
        a1.x += v1.x; a1.y += v1.y; a1.z += v1.z; a1.w += v1.w;
    }
    if (j < end) {
        int s0 = g_csr[j];
        float4 v0 = *(const float4*)(z + (size_t)s0 * 64 + gl * 4);
        a0.x += v0.x; a0.y += v0.y; a0.z += v0.z; a0.w += v0.w;
    }
    const float inv = g_invd[node];
    float4 o = *(const float4*)(out + (size_t)node * 64 + gl * 4);
    o.x += (a0.x + a1.x) * inv;
    o.y += (a0.y + a1.y) * inv;
    o.z += (a0.z + a1.z) * inv;
    o.w += (a0.w + a1.w) * inv;
    *(float4*)(out + (size_t)node * 64 + gl * 4) = o;
}

// ================= bf16x2-split WMMA GEMM (R10, HMMA-bound, known-good) =================
__device__ __forceinline__ void split_store8(__nv_bfloat16* __restrict__ hi,
                                             __nv_bfloat16* __restrict__ lo,
                                             float4 v0, float4 v1) {
    float f[8] = {v0.x, v0.y, v0.z, v0.w, v1.x, v1.y, v1.z, v1.w};
    #pragma unroll
    for (int i = 0; i < 8; i++) {
        __nv_bfloat16 h = __float2bfloat16_rn(f[i]);
        __nv_bfloat16 l = __float2bfloat16_rn(f[i] - __bfloat162float(h));
        hi[i] = h;
        lo[i] = l;
    }
}

template <int BN>
__global__ __launch_bounds__(512)
void gemm_wmma_kernel(const float* __restrict__ A0,
                      const float* __restrict__ A1,
                      const float* __restrict__ W,
                      const float* __restrict__ bias,
                      float* __restrict__ out,
                      int M, int d, int Nout, int relu) {
    constexpr int BM  = 128;
    constexpr int BK  = 32;
    constexpr int LDT = 40;
    constexpr int WN  = BN / 4;
    constexpr int FN  = WN / 16;
    constexpr int LDC = BN + 4;

    extern __shared__ char smraw[];
    __nv_bfloat16* aHi = (__nv_bfloat16*)smraw;
    __nv_bfloat16* aLo = aHi + BM * LDT;
    __nv_bfloat16* bHi = aLo + BM * LDT;
    __nv_bfloat16* bLo = bHi + BN * LDT;
    float* Cs = (float*)smraw;

    const int tid = threadIdx.x;
    const int wid = tid >> 5;
    const int m0 = (wid >> 2) * 32;
    const int n0 = (wid & 3) * WN;
    const int bm = blockIdx.x * BM;
    const int bn = blockIdx.y * BN;
    const int K = 2 * d;
    const int nsteps = K / BK;

    wmma::fragment<wmma::accumulator, 16, 16, 16, float> acc[2][FN];
    #pragma unroll
    for (int fm = 0; fm < 2; fm++)
        #pragma unroll
        for (int fn = 0; fn < FN; fn++)
            wmma::fill_fragment(acc[fm][fn], 0.f);

    const int ar = tid >> 2;
    const int ac = (tid & 3) * 8;
    const int br = (BN == 128) ? (tid >> 2) : (tid >> 3);
    const int bc = (BN == 128) ? (tid & 3) * 8 : (tid & 7) * 4;
    constexpr int NB4 = (BN == 128) ? 2 : 1;

    float4 ra[2], rb[2];

    auto loadA = [&](int k0) {
        int gm = bm + ar;
        if (gm < M) {
            const float* p = (k0 < d) ? (A0 + (size_t)gm * d + k0 + ac)
                                      : (A1 + (size_t)gm * d + (k0 - d) + ac);
            ra[0] = *(const float4*)(p);
            ra[1] = *(const float4*)(p + 4);
        } else {
            ra[0] = ra[1] = make_float4(0.f, 0.f, 0.f, 0.f);
        }
    };
    auto loadB = [&](int k0) {
        const float* p = W + (size_t)(bn + br) * K + k0 + bc;
        rb[0] = *(const float4*)(p);
        if (NB4 == 2) rb[1] = *(const float4*)(p + 4);
    };

    loadA(0);
    loadB(0);

    for (int s = 0; s < nsteps; s++) {
        __syncthreads();
        split_store8(aHi + ar * LDT + ac, aLo + ar * LDT + ac, ra[0], ra[1]);
        if (NB4 == 2) {
            split_store8(bHi + br * LDT + bc, bLo + br * LDT + bc, rb[0], rb[1]);
        } else {
            float f[4] = {rb[0].x, rb[0].y, rb[0].z, rb[0].w};
            #pragma unroll
            for (int i = 0; i < 4; i++) {
                __nv_bfloat16 h = __float2bfloat16_rn(f[i]);
                __nv_bfloat16 l = __float2bfloat16_rn(f[i] - __bfloat162float(h));
                bHi[br * LDT + bc + i] = h;
                bLo[br * LDT + bc + i] = l;
            }
        }
        __syncthreads();

        if (s + 1 < nsteps) {
            loadA((s + 1) * BK);
            loadB((s + 1) * BK);
        }

        #pragma unroll
        for (int ks = 0; ks < BK; ks += 16) {
            wmma::fragment<wmma::matrix_a, 16, 16, 16, __nv_bfloat16, wmma::row_major> a_hi[2], a_lo[2];
            #pragma unroll
            for (int fm = 0; fm < 2; fm++) {
                wmma::load_matrix_sync(a_hi[fm], aHi + (m0 + fm * 16) * LDT + ks, LDT);
                wmma::load_matrix_sync(a_lo[fm], aLo + (m0 + fm * 16) * LDT + ks, LDT);
            }
            #pragma unroll
            for (int fn = 0; fn < FN; fn++) {
                wmma::fragment<wmma::matrix_b, 16, 16, 16, __nv_bfloat16, wmma::col_major> b_hi, b_lo;
                wmma::load_matrix_sync(b_hi, bHi + (n0 + fn * 16) * LDT + ks, LDT);
                wmma::load_matrix_sync(b_lo, bLo + (n0 + fn * 16) * LDT + ks, LDT);
                #pragma unroll
                for (int fm = 0; fm < 2; fm++) {
                    wmma::mma_sync(acc[fm][fn], a_hi[fm], b_hi, acc[fm][fn]);
                    wmma::mma_sync(acc[fm][fn], a_hi[fm], b_lo, acc[fm][fn]);
                    wmma::mma_sync(acc[fm][fn], a_lo[fm], b_hi, acc[fm][fn]);
                }
            }
        }
    }

    __syncthreads();
    #pragma unroll
    for (int fm = 0; fm < 2; fm++)
        #pragma unroll
        for (int fn = 0; fn < FN; fn++)
            wmma::store_matrix_sync(Cs + (m0 + fm * 16) * LDC + n0 + fn * 16,
                                    acc[fm][fn], LDC, wmma::mem_row_major);
    __syncthreads();

    {
        constexpr int CPT = (BM * BN) / 512;
        constexpr int NF4 = CPT / 4;
        const int row = tid >> 2;
        const int c0 = (tid & 3) * CPT;
        const int gm = bm + row;
        if (gm < M) {
            #pragma unroll
            for (int j = 0; j < NF4; j++) {
                int c = c0 + j * 4;
                float4 v = *(const float4*)(Cs + row * LDC + c);
                v.x += bias[bn + c + 0];
                v.y += bias[bn + c + 1];
                v.z += bias[bn + c + 2];
                v.w += bias[bn + c + 3];
                if (relu) {
                    v.x = fmaxf(v.x, 0.f); v.y = fmaxf(v.y, 0.f);
                    v.z = fmaxf(v.z, 0.f); v.w = fmaxf(v.w, 0.f);
                }
                *(float4*)(out + (size_t)gm * Nout + bn + c) = v;
            }
        }
    }
}

// -------- Layer-3 fused GEMM: BN=128 over stacked [W3self ; W3neigh] --------
__global__ __launch_bounds__(512)
void gemm_wmma_l3_kernel(const float* __restrict__ A,
                         const float* __restrict__ W3,
                         const float* __restrict__ bias,
                         float* __restrict__ out,
                         float* __restrict__ z,
                         int M) {
    constexpr int BM  = 128;
    constexpr int BN  = 128;
    constexpr int BK  = 32;
    constexpr int LDT = 40;
    constexpr int WN  = 32;
    constexpr int FN  = 2;
    constexpr int LDC = BN + 4;
    constexpr int Kc  = 256;

    extern __shared__ char smraw[];
    __nv_bfloat16* aHi = (__nv_bfloat16*)smraw;
    __nv_bfloat16* aLo = aHi + BM * LDT;
    __nv_bfloat16* bHi = aLo + BM * LDT;
    __nv_bfloat16* bLo = bHi + BN * LDT;
    float* Cs = (float*)smraw;

    const int tid = threadIdx.x;
    const int wid = tid >> 5;
    const int m0 = (wid >> 2) * 32;
    const int n0 = (wid & 3) * WN;
    const int bm = blockIdx.x * BM;
    const int nsteps = Kc / BK;

    wmma::fragment<wmma::accumulator, 16, 16, 16, float> acc[2][FN];
    #pragma unroll
    for (int fm = 0; fm < 2; fm++)
        #pragma unroll
        for (int fn = 0; fn < FN; fn++)
            wmma::fill_fragment(acc[fm][fn], 0.f);

    const int ar = tid >> 2;
    const int ac = (tid & 3) * 8;
    const int br = tid >> 2;
    const int bc = (tid & 3) * 8;
    const int wrow = br & 63;
    const int woff = (br >> 6) * 256;

    float4 ra[2], rb[2];

    auto loadA = [&](int k0) {
        int gm = bm + ar;
        if (gm < M) {
            const float* p = A + (size_t)gm * Kc + k0 + ac;
            ra[0] = *(const float4*)(p);
            ra[1] = *(const float4*)(p + 4);
        } else {
            ra[0] = ra[1] = make_float4(0.f, 0.f, 0.f, 0.f);
        }
    };
    auto loadB = [&](int k0) {
        const float* p = W3 + (size_t)wrow * 512 + woff + k0 + bc;
        rb[0] = *(const float4*)(p);
        rb[1] = *(const float4*)(p + 4);
    };

    loadA(0);
    loadB(0);

    for (int s = 0; s < nsteps; s++) {
        __syncthreads();
        split_store8(aHi + ar * LDT + ac, aLo + ar * LDT + ac, ra[0], ra[1]);
        split_store8(bHi + br * LDT + bc, bLo + br * LDT + bc, rb[0], rb[1]);
        __syncthreads();

        if (s + 1 < nsteps) {
            loadA((s + 1) * BK);
            loadB((s + 1) * BK);
        }

        #pragma unroll
        for (int ks = 0; ks < BK; ks += 16) {
            wmma::fragment<wmma::matrix_a, 16, 16, 16, __nv_bfloat16, wmma::row_major> a_hi[2], a_lo[2];
            #pragma unroll
            for (int fm = 0; fm < 2; fm++) {
                wmma::load_matrix_sync(a_hi[fm], aHi + (m0 + fm * 16) * LDT + ks, LDT);
                wmma::load_matrix_sync(a_lo[fm], aLo + (m0 + fm * 16) * LDT + ks, LDT);
            }
            #pragma unroll
            for (int fn = 0; fn < FN; fn++) {
                wmma::fragment<wmma::matrix_b, 16, 16, 16, __nv_bfloat16, wmma::col_major> b_hi, b_lo;
                wmma::load_matrix_sync(b_hi, bHi + (n0 + fn * 16) * LDT + ks, LDT);
                wmma::load_matrix_sync(b_lo, bLo + (n0 + fn * 16) * LDT + ks, LDT);
                #pragma unroll
                for (int fm = 0; fm < 2; fm++) {
                    wmma::mma_sync(acc[fm][fn], a_hi[fm], b_hi, acc[fm][fn]);
                    wmma::mma_sync(acc[fm][fn], a_hi[fm], b_lo, acc[fm][fn]);
                    wmma::mma_sync(acc[fm][fn], a_lo[fm], b_hi, acc[fm][fn]);
                }
            }
        }
    }

    __syncthreads();
    #pragma unroll
    for (int fm = 0; fm < 2; fm++)
        #pragma unroll
        for (int fn = 0; fn < FN; fn++)
            wmma::store_matrix_sync(Cs + (m0 + fm * 16) * LDC + n0 + fn * 16,
                                    acc[fm][fn], LDC, wmma::mem_row_major);
    __syncthreads();

    {
        const int row = tid >> 2;
        const int c0 = (tid & 3) * 32;
        const int gm = bm + row;
        if (gm < M) {
            if (c0 < 64) {
                #pragma unroll
                for (int j = 0; j < 8; j++) {
                    int c = c0 + j * 4;
                    float4 v = *(const float4*)(Cs + row * LDC + c);
                    v.x += bias[c + 0];
                    v.y += bias[c + 1];
                    v.z += bias[c + 2];
                    v.w += bias[c + 3];
                    *(float4*)(out + (size_t)gm * 64 + c) = v;
                }
            } else {
                #pragma unroll
                for (int j = 0; j < 8; j++) {
                    int c = c0 + j * 4;
                    float4 v = *(const float4*)(Cs + row * LDC + c);
                    *(float4*)(z + (size_t)gm * 64 + (c - 64)) = v;
                }
            }
        }
    }
}

extern "C" void kernel_launch(void* const* d_in, const int* in_sizes, int n_in,
                              void* d_out, int out_size) {
    const float* x   = (const float*)d_in[0];
    const int*   src = (const int*)d_in[1];
    const int*   dst = (const int*)d_in[2];
    const float* W1 = (const float*)d_in[3];
    const float* b1 = (const float*)d_in[4];
    const float* W2 = (const float*)d_in[5];
    const float* b2 = (const float*)d_in[6];
    const float* W3 = (const float*)d_in[7];
    const float* b3 = (const float*)d_in[8];
    float* out = (float*)d_out;

    const int E = in_sizes[1];
    const int M = in_sizes[0] / IN_FEATS;   // 100000

    float *h1, *h2, *hN;
    int *deg, *rowptr;
    cudaGetSymbolAddress((void**)&h1,     g_h1);
    cudaGetSymbolAddress((void**)&h2,     g_h2);
    cudaGetSymbolAddress((void**)&hN,     g_hN);
    cudaGetSymbolAddress((void**)&deg,    g_deg);
    cudaGetSymbolAddress((void**)&rowptr, g_rowptr);

    const int SMEM128 = 128 * 132 * 4;  // 67584
    cudaFuncSetAttribute(gemm_wmma_kernel<128>,
                         cudaFuncAttributeMaxDynamicSharedMemorySize, SMEM128);
    cudaFuncSetAttribute(gemm_wmma_l3_kernel,
                         cudaFuncAttributeMaxDynamicSharedMemorySize, SMEM128);

    const int T = 256;
    const int gx = (M + 127) / 128;

    // degrees + CSR build (recomputed every call: deterministic work)
    zero_int_kernel<<<(M + T - 1) / T, T>>>(deg, M);
    deg_kernel<<<(E + T - 1) / T, T>>>(dst, E);
    invd_kernel<<<(M + T - 1) / T, T>>>(M);

    int nb = (M + SCAN_T - 1) / SCAN_T;
    scan1_kernel<<<nb, SCAN_T>>>(rowptr, M);
    scan2_kernel<<<1, 128>>>(nb);
    scan3_kernel<<<(M + T - 1) / T, T>>>(M, E);
    scatter_kernel<<<(E + T - 1) / T, T>>>(src, dst, E);

    // ---- Layer 1: d=128, Nout=256, relu (warp per node, 32 lanes x float4) ----
    {
        long long th = (long long)M * 32;
        agg_group_kernel<32, 128><<<(int)((th + 255) / 256), 256>>>(x, hN);
        gemm_wmma_kernel<128><<<dim3(gx, 2), 512, SMEM128>>>(x, hN, W1, b1, h1, M, IN_FEATS, 256, 1);
    }
    // ---- Layer 2: d=256, Nout=256, relu (64-lane group per node) ----
    {
        long long th = (long long)M * 64;
        agg_group_kernel<64, 256><<<(int)((th + 255) / 256), 256>>>(h1, hN);
        gemm_wmma_kernel<128><<<dim3(gx, 2), 512, SMEM128>>>(h1, hN, W2, b2, h2, M, 256, 256, 1);
    }
    // ---- Layer 3: Nout=64, output-side aggregation (16-lane groups) ----
    {
        gemm_wmma_l3_kernel<<<gx, 512, SMEM128>>>(h2, W3, b3, out, hN, M);
        long long th = (long long)M * 16;
        agg_add64_kernel<<<(int)((th + 255) / 256), 256>>>(hN, out);
    }
}

// round 14
// speedup vs baseline: 1.4448x; 1.0408x over previous
#include <cuda_runtime.h>
#include <cuda_bf16.h>
#include <mma.h>
#include <cstdint>

using namespace nvcuda;

#define N_NODES 100000
#define N_EDGES_MAX 1600000
#define IN_FEATS 128
#define HMAX 256

// Scratch (allocation-free rule: __device__ globals)
__device__ float g_h1[(size_t)N_NODES * HMAX];
__device__ float g_h2[(size_t)N_NODES * HMAX];
__device__ float g_hN[(size_t)N_NODES * HMAX];
__device__ int   g_deg[N_NODES];
__device__ float g_invd[N_NODES];
__device__ int   g_rowptr[N_NODES + 1];
__device__ int   g_pos[N_NODES];
__device__ int   g_csr[N_EDGES_MAX];
__device__ int   g_bsum[128];

// ---------------- degree ----------------
__global__ void zero_int_kernel(int* __restrict__ p, int n) {
    int i = blockIdx.x * blockDim.x + threadIdx.x;
    if (i < n) p[i] = 0;
}

__global__ void deg_kernel(const int* __restrict__ dst, int E) {
    int i = blockIdx.x * blockDim.x + threadIdx.x;
    if (i < E) atomicAdd(&g_deg[dst[i]], 1);
}

// ---------------- prefix sum (CSR rowptr) ----------------
#define SCAN_T 1024

__global__ void scan1_kernel(int* __restrict__ excl, int n) {
    __shared__ int s[SCAN_T];
    int i = blockIdx.x * SCAN_T + threadIdx.x;
    int v = (i < n) ? g_deg[i] : 0;
    s[threadIdx.x] = v;
    __syncthreads();
    for (int off = 1; off < SCAN_T; off <<= 1) {
        int t = (threadIdx.x >= off) ? s[threadIdx.x - off] : 0;
        __syncthreads();
        s[threadIdx.x] += t;
        __syncthreads();
    }
    if (i < n) excl[i] = s[threadIdx.x] - v;
    if (threadIdx.x == SCAN_T - 1) g_bsum[blockIdx.x] = s[SCAN_T - 1];
}

__global__ void scan2_kernel(int nb) {
    __shared__ int s[128];
    int v = (threadIdx.x < nb) ? g_bsum[threadIdx.x] : 0;
    s[threadIdx.x] = v;
    __syncthreads();
    for (int off = 1; off < 128; off <<= 1) {
        int t = (threadIdx.x >= off) ? s[threadIdx.x - off] : 0;
        __syncthreads();
        s[threadIdx.x] += t;
        __syncthreads();
    }
    if (threadIdx.x < nb) g_bsum[threadIdx.x] = s[threadIdx.x] - v;  // exclusive
}

// scan3 + invd fused
__global__ void scan3_kernel(int n, int E) {
    int i = blockIdx.x * blockDim.x + threadIdx.x;
    if (i < n) {
        int r = g_rowptr[i] + g_bsum[i / SCAN_T];
        g_rowptr[i] = r;
        g_pos[i] = r;
        g_invd[i] = 1.0f / fmaxf((float)g_deg[i], 1.0f);
    }
    if (i == 0) g_rowptr[n] = E;
}

__global__ void scatter_kernel(const int* __restrict__ src,
                               const int* __restrict__ dst, int E) {
    int i = blockIdx.x * blockDim.x + threadIdx.x;
    if (i < E) {
        int t = dst[i];
        int slot = atomicAdd(&g_pos[t], 1);
        g_csr[slot] = src[i];
    }
}

// ============ sync-free group-per-node mean aggregation (LDG.128) ============
template <int GROUP_LANES, int D>
__global__ __launch_bounds__(256)
void agg_group_kernel(const float* __restrict__ h, float* __restrict__ hN) {
    const int gt = blockIdx.x * blockDim.x + threadIdx.x;
    const int node = gt / GROUP_LANES;
    const int gl = gt % GROUP_LANES;
    if (node >= N_NODES) return;
    const int start = g_rowptr[node];
    const int end   = g_rowptr[node + 1];
    float4 a0 = make_float4(0.f, 0.f, 0.f, 0.f);
    float4 a1 = make_float4(0.f, 0.f, 0.f, 0.f);
    int j = start;
    for (; j + 2 <= end; j += 2) {
        int s0 = g_csr[j];
        int s1 = g_csr[j + 1];
        float4 v0 = *(const float4*)(h + (size_t)s0 * D + gl * 4);
        float4 v1 = *(const float4*)(h + (size_t)s1 * D + gl * 4);
        a0.x += v0.x; a0.y += v0.y; a0.z += v0.z; a0.w += v0.w;
        a1.x += v1.x; a1.y += v1.y; a1.z += v1.z; a1.w += v1.w;
    }
    if (j < end) {
        int s0 = g_csr[j];
        float4 v0 = *(const float4*)(h + (size_t)s0 * D + gl * 4);
        a0.x += v0.x; a0.y += v0.y; a0.z += v0.z; a0.w += v0.w;
    }
    const float inv = g_invd[node];
    float4 r;
    r.x = (a0.x + a1.x) * inv;
    r.y = (a0.y + a1.y) * inv;
    r.z = (a0.z + a1.z) * inv;
    r.w = (a0.w + a1.w) * inv;
    *(float4*)(hN + (size_t)node * D + gl * 4) = r;
}

// L3 output-side: out[node] += mean(z[nbrs]), width 64, 16-lane groups.
__global__ __launch_bounds__(256)
void agg_add64_kernel(const float* __restrict__ z, float* __restrict__ out) {
    const int gt = blockIdx.x * blockDim.x + threadIdx.x;
    const int node = gt >> 4;
    const int gl = gt & 15;
    if (node >= N_NODES) return;
    const int start = g_rowptr[node];
    const int end   = g_rowptr[node + 1];
    float4 a0 = make_float4(0.f, 0.f, 0.f, 0.f);
    float4 a1 = make_float4(0.f, 0.f, 0.f, 0.f);
    int j = start;
    for (; j + 2 <= end; j += 2) {
        int s0 = g_csr[j];
        int s1 = g_csr[j + 1];
        float4 v0 = *(const float4*)(z + (size_t)s0 * 64 + gl * 4);
        float4 v1 = *(const float4*)(z + (size_t)s1 * 64 + gl * 4);
        a0.x += v0.x; a0.y += v0.y; a0.z += v0.z; a0.w += v0.w;
        a1.x += v1.x; a1.y += v1.y; a1.z += v1.z; a1.w += v1.w;
    }
    if (j < end) {
        int s0 = g_csr[j];
        float4 v0 = *(const float4*)(z + (size_t)s0 * 64 + gl * 4);
        a0.x += v0.x; a0.y += v0.y; a0.z += v0.z; a0.w += v0.w;
    }
    const float inv = g_invd[node];
    float4 o = *(const float4*)(out + (size_t)node * 64 + gl * 4);
    o.x += (a0.x + a1.x) * inv;
    o.y += (a0.y + a1.y) * inv;
    o.z += (a0.z + a1.z) * inv;
    o.w += (a0.w + a1.w) * inv;
    *(float4*)(out + (size_t)node * 64 + gl * 4) = o;
}

// ========== bf16x2-split WMMA GEMM, double-buffered smem (1 sync/step) ==========
#define G_LDT 40
#define G_PLANE (128 * G_LDT)            // bf16 elems per plane
#define G_BUF (4 * G_PLANE)              // elems per stage (aHi,aLo,bHi,bLo)

__device__ __forceinline__ void split_store8(__nv_bfloat16* __restrict__ hi,
                                             __nv_bfloat16* __restrict__ lo,
                                             float4 v0, float4 v1) {
    float f[8] = {v0.x, v0.y, v0.z, v0.w, v1.x, v1.y, v1.z, v1.w};
    #pragma unroll
    for (int i = 0; i < 8; i++) {
        __nv_bfloat16 h = __float2bfloat16_rn(f[i]);
        __nv_bfloat16 l = __float2bfloat16_rn(f[i] - __bfloat162float(h));
        hi[i] = h;
        lo[i] = l;
    }
}

__device__ __forceinline__ void gemm_compute_step(
    const __nv_bfloat16* __restrict__ buf, int m0, int n0,
    wmma::fragment<wmma::accumulator, 16, 16, 16, float> (&acc)[2][2]) {
    const __nv_bfloat16* aHi = buf;
    const __nv_bfloat16* aLo = buf + G_PLANE;
    const __nv_bfloat16* bHi = buf + 2 * G_PLANE;
    const __nv_bfloat16* bLo = buf + 3 * G_PLANE;
    #pragma unroll
    for (int ks = 0; ks < 32; ks += 16) {
        wmma::fragment<wmma::matrix_a, 16, 16, 16, __nv_bfloat16, wmma::row_major> a_hi[2], a_lo[2];
        #pragma unroll
        for (int fm = 0; fm < 2; fm++) {
            wmma::load_matrix_sync(a_hi[fm], aHi + (m0 + fm * 16) * G_LDT + ks, G_LDT);
            wmma::load_matrix_sync(a_lo[fm], aLo + (m0 + fm * 16) * G_LDT + ks, G_LDT);
        }
        #pragma unroll
        for (int fn = 0; fn < 2; fn++) {
            wmma::fragment<wmma::matrix_b, 16, 16, 16, __nv_bfloat16, wmma::col_major> b_hi, b_lo;
            wmma::load_matrix_sync(b_hi, bHi + (n0 + fn * 16) * G_LDT + ks, G_LDT);
            wmma::load_matrix_sync(b_lo, bLo + (n0 + fn * 16) * G_LDT + ks, G_LDT);
            #pragma unroll
            for (int fm = 0; fm < 2; fm++) {
                wmma::mma_sync(acc[fm][fn], a_hi[fm], b_hi, acc[fm][fn]);
                wmma::mma_sync(acc[fm][fn], a_hi[fm], b_lo, acc[fm][fn]);
                wmma::mma_sync(acc[fm][fn], a_lo[fm], b_hi, acc[fm][fn]);
            }
        }
    }
}

// Layers 1-2 GEMM: out = [A0|A1]@W^T + bias (+relu). CTA 128x128, BK=32.
__global__ __launch_bounds__(512)
void gemm_wmma_kernel(const float* __restrict__ A0,
                      const float* __restrict__ A1,
                      const float* __restrict__ W,
                      const float* __restrict__ bias,
                      float* __restrict__ out,
                      int M, int d, int Nout, int relu) {
    constexpr int LDC = 132;
    extern __shared__ char smraw[];
    __nv_bfloat16* tiles = (__nv_bfloat16*)smraw;
    float* Cs = (float*)smraw;

    const int tid = threadIdx.x;
    const int wid = tid >> 5;
    const int m0 = (wid >> 2) * 32;
    const int n0 = (wid & 3) * 32;
    const int bm = blockIdx.x * 128;
    const int bn = blockIdx.y * 128;
    const int K = 2 * d;
    const int nsteps = K / 32;

    wmma::fragment<wmma::accumulator, 16, 16, 16, float> acc[2][2];
    #pragma unroll
    for (int fm = 0; fm < 2; fm++)
        #pragma unroll
        for (int fn = 0; fn < 2; fn++)
            wmma::fill_fragment(acc[fm][fn], 0.f);

    const int ar = tid >> 2;            // 128 rows, 4 thr/row, 8 cols each
    const int ac = (tid & 3) * 8;
    const int gm = bm + ar;

    float4 ra[2], rb[2];

    auto loadA = [&](int k0) {
        if (gm < M) {
            const float* p = (k0 < d) ? (A0 + (size_t)gm * d + k0 + ac)
                                      : (A1 + (size_t)gm * d + (k0 - d) + ac);
            ra[0] = *(const float4*)(p);
            ra[1] = *(const float4*)(p + 4);
        } else {
            ra[0] = ra[1] = make_float4(0.f, 0.f, 0.f, 0.f);
        }
    };
    auto loadB = [&](int k0) {
        const float* p = W + (size_t)(bn + ar) * K + k0 + ac;
        rb[0] = *(const float4*)(p);
        rb[1] = *(const float4*)(p + 4);
    };
    auto storeStage = [&](int s) {
        __nv_bfloat16* buf = tiles + (size_t)(s & 1) * G_BUF;
        split_store8(buf + ar * G_LDT + ac,               buf + G_PLANE + ar * G_LDT + ac, ra[0], ra[1]);
        split_store8(buf + 2 * G_PLANE + ar * G_LDT + ac, buf + 3 * G_PLANE + ar * G_LDT + ac, rb[0], rb[1]);
    };

    loadA(0); loadB(0);
    storeStage(0);
    __syncthreads();

    for (int s = 0; s < nsteps; s++) {
        if (s + 1 < nsteps) { loadA((s + 1) * 32); loadB((s + 1) * 32); }
        gemm_compute_step(tiles + (size_t)(s & 1) * G_BUF, m0, n0, acc);
        if (s + 1 < nsteps) storeStage(s + 1);
        __syncthreads();
    }

    // ---- epilogue: frags -> Cs (aliases buf0) -> bias/relu -> global ----
    #pragma unroll
    for (int fm = 0; fm < 2; fm++)
        #pragma unroll
        for (int fn = 0; fn < 2; fn++)
            wmma::store_matrix_sync(Cs + (m0 + fm * 16) * LDC + n0 + fn * 16,
                                    acc[fm][fn], LDC, wmma::mem_row_major);
    __syncthreads();

    {
        const int row = tid >> 2;
        const int c0 = (tid & 3) * 32;
        const int gmo = bm + row;
        if (gmo < M) {
            #pragma unroll
            for (int j = 0; j < 8; j++) {
                int c = c0 + j * 4;
                float4 v = *(const float4*)(Cs + row * LDC + c);
                v.x += bias[bn + c + 0];
                v.y += bias[bn + c + 1];
                v.z += bias[bn + c + 2];
                v.w += bias[bn + c + 3];
                if (relu) {
                    v.x = fmaxf(v.x, 0.f); v.y = fmaxf(v.y, 0.f);
                    v.z = fmaxf(v.z, 0.f); v.w = fmaxf(v.w, 0.f);
                }
                *(float4*)(out + (size_t)gmo * Nout + bn + c) = v;
            }
        }
    }
}

// L3 fused GEMM: B = stacked [W3self ; W3neigh] (virtual 128 rows), K=256.
// cols 0..63 -> out (+bias), cols 64..127 -> z.
__global__ __launch_bounds__(512)
void gemm_wmma_l3_kernel(const float* __restrict__ A,
                         const float* __restrict__ W3,
                         const float* __restrict__ bias,
                         float* __restrict__ out,
                         float* __restrict__ z,
                         int M) {
    constexpr int LDC = 132;
    constexpr int Kc = 256;
    extern __shared__ char smraw[];
    __nv_bfloat16* tiles = (__nv_bfloat16*)smraw;
    float* Cs = (float*)smraw;

    const int tid = threadIdx.x;
    const int wid = tid >> 5;
    const int m0 = (wid >> 2) * 32;
    const int n0 = (wid & 3) * 32;
    const int bm = blockIdx.x * 128;
    const int nsteps = Kc / 32;   // 8

    wmma::fragment<wmma::accumulator, 16, 16, 16, float> acc[2][2];
    #pragma unroll
    for (int fm = 0; fm < 2; fm++)
        #pragma unroll
        for (int fn = 0; fn < 2; fn++)
            wmma::fill_fragment(acc[fm][fn], 0.f);

    const int ar = tid >> 2;
    const int ac = (tid & 3) * 8;
    const int gm = bm + ar;
    const int wrow = ar & 63;
    const int woff = (ar >> 6) * 256;

    float4 ra[2], rb[2];

    auto loadA = [&](int k0) {
        if (gm < M) {
            const float* p = A + (size_t)gm * Kc + k0 + ac;
            ra[0] = *(const float4*)(p);
            ra[1] = *(const float4*)(p + 4);
        } else {
            ra[0] = ra[1] = make_float4(0.f, 0.f, 0.f, 0.f);
        }
    };
    auto loadB = [&](int k0) {
        const float* p = W3 + (size_t)wrow * 512 + woff + k0 + ac;
        rb[0] = *(const float4*)(p);
        rb[1] = *(const float4*)(p + 4);
    };
    auto storeStage = [&](int s) {
        __nv_bfloat16* buf = tiles + (size_t)(s & 1) * G_BUF;
        split_store8(buf + ar * G_LDT + ac,               buf + G_PLANE + ar * G_LDT + ac, ra[0], ra[1]);
        split_store8(buf + 2 * G_PLANE + ar * G_LDT + ac, buf + 3 * G_PLANE + ar * G_LDT + ac, rb[0], rb[1]);
    };

    loadA(0); loadB(0);
    storeStage(0);
    __syncthreads();

    for (int s = 0; s < nsteps; s++) {
        if (s + 1 < nsteps) { loadA((s + 1) * 32); loadB((s + 1) * 32); }
        gemm_compute_step(tiles + (size_t)(s & 1) * G_BUF, m0, n0, acc);
        if (s + 1 < nsteps) storeStage(s + 1);
        __syncthreads();
    }

    #pragma unroll
    for (int fm = 0; fm < 2; fm++)
        #pragma unroll
        for (int fn = 0; fn < 2; fn++)
            wmma::store_matrix_sync(Cs + (m0 + fm * 16) * LDC + n0 + fn * 16,
                                    acc[fm][fn], LDC, wmma::mem_row_major);
    __syncthreads();

    {
        const int row = tid >> 2;
        const int c0 = (tid & 3) * 32;   // {0,32}: self -> out; {64,96}: -> z
        const int gmo = bm + row;
        if (gmo < M) {
            if (c0 < 64) {
                #pragma unroll
                for (int j = 0; j < 8; j++) {
                    int c = c0 + j * 4;
                    float4 v = *(const float4*)(Cs + row * LDC + c);
                    v.x += bias[c + 0];
                    v.y += bias[c + 1];
                    v.z += bias[c + 2];
                    v.w += bias[c + 3];
                    *(float4*)(out + (size_t)gmo * 64 + c) = v;
                }
            } else {
                #pragma unroll
                for (int j = 0; j < 8; j++) {
                    int c = c0 + j * 4;
                    float4 v = *(const float4*)(Cs + row * LDC + c);
                    *(float4*)(z + (size_t)gmo * 64 + (c - 64)) = v;
                }
            }
        }
    }
}

extern "C" void kernel_launch(void* const* d_in, const int* in_sizes, int n_in,
                              void* d_out, int out_size) {
    const float* x   = (const float*)d_in[0];
    const int*   src = (const int*)d_in[1];
    const int*   dst = (const int*)d_in[2];
    const float* W1 = (const float*)d_in[3];
    const float* b1 = (const float*)d_in[4];
    const float* W2 = (const float*)d_in[5];
    const float* b2 = (const float*)d_in[6];
    const float* W3 = (const float*)d_in[7];
    const float* b3 = (const float*)d_in[8];
    float* out = (float*)d_out;

    const int E = in_sizes[1];
    const int M = in_sizes[0] / IN_FEATS;   // 100000

    float *h1, *h2, *hN;
    int *deg, *rowptr;
    cudaGetSymbolAddress((void**)&h1,     g_h1);
    cudaGetSymbolAddress((void**)&h2,     g_h2);
    cudaGetSymbolAddress((void**)&hN,     g_hN);
    cudaGetSymbolAddress((void**)&deg,    g_deg);
    cudaGetSymbolAddress((void**)&rowptr, g_rowptr);

    const int SMEM_G = 2 * G_BUF * 2;   // 81920 bytes (2 stages x 4 planes)
    cudaFuncSetAttribute(gemm_wmma_kernel,
                         cudaFuncAttributeMaxDynamicSharedMemorySize, SMEM_G);
    cudaFuncSetAttribute(gemm_wmma_l3_kernel,
                         cudaFuncAttributeMaxDynamicSharedMemorySize, SMEM_G);

    const int T = 256;
    const int gx = (M + 127) / 128;

    // degrees + CSR build (recomputed every call: deterministic work)
    zero_int_kernel<<<(M + T - 1) / T, T>>>(deg, M);
    deg_kernel<<<(E + T - 1) / T, T>>>(dst, E);

    int nb = (M + SCAN_T - 1) / SCAN_T;
    scan1_kernel<<<nb, SCAN_T>>>(rowptr, M);
    scan2_kernel<<<1, 128>>>(nb);
    scan3_kernel<<<(M + T - 1) / T, T>>>(M, E);   // + invd fused
    scatter_kernel<<<(E + T - 1) / T, T>>>(src, dst, E);

    // ---- Layer 1: d=128, Nout=256, relu (warp per node) ----
    {
        long long th = (long long)M * 32;
        agg_group_kernel<32, 128><<<(int)((th + 255) / 256), 256>>>(x, hN);
        gemm_wmma_kernel<<<dim3(gx, 2), 512, SMEM_G>>>(x, hN, W1, b1, h1, M, IN_FEATS, 256, 1);
    }
    // ---- Layer 2: d=256, Nout=256, relu (64-lane group per node) ----
    {
        long long th = (long long)M * 64;
        agg_group_kernel<64, 256><<<(int)((th + 255) / 256), 256>>>(h1, hN);
        gemm_wmma_kernel<<<dim3(gx, 2), 512, SMEM_G>>>(h1, hN, W2, b2, h2, M, 256, 256, 1);
    }
    // ---- Layer 3: Nout=64, output-side aggregation (16-lane groups) ----
    {
        gemm_wmma_l3_kernel<<<gx, 512, SMEM_G>>>(h2, W3, b3, out, hN, M);
        long long th = (long long)M * 16;
        agg_add64_kernel<<<(int)((th + 255) / 256), 256>>>(hN, out);
    }
}